// round 1
// baseline (speedup 1.0000x reference)
#include <cuda_runtime.h>

// SimpleRNN: B=1024, T=2048, I=1, H=64, O=1
//   h_t = tanh(h_{t-1} @ W_h^T + x_t @ W_x^T);  y_t = h_t @ W_y^T
// Mapping: one warp per batch row, persistent over all T steps.
// Lane L owns hidden units j0=2L, j1=2L+1. W_h rows held in registers as
// packed f32x2 pairs; dot product packed along K via fma.rn.f32x2.
// h state double-buffered in shared memory (warp-private region).

#define BB 1024
#define TT 2048
#define HH 64
#define WARPS_PER_CTA 8
#define THREADS (32 * WARPS_PER_CTA)

typedef unsigned long long u64;

__device__ __forceinline__ u64 fma2(u64 a, u64 b, u64 c) {
    u64 d;
    asm("fma.rn.f32x2 %0, %1, %2, %3;" : "=l"(d) : "l"(a), "l"(b), "l"(c));
    return d;
}
__device__ __forceinline__ u64 pack2(float lo, float hi) {
    u64 r;
    asm("mov.b64 %0, {%1, %2};" : "=l"(r) : "f"(lo), "f"(hi));
    return r;
}
__device__ __forceinline__ void unpack2(u64 v, float& lo, float& hi) {
    asm("mov.b64 {%0, %1}, %2;" : "=f"(lo), "=f"(hi) : "l"(v));
}
__device__ __forceinline__ float tanh_fast(float x) {
    float y;
    asm("tanh.approx.f32 %0, %1;" : "=f"(y) : "f"(x));
    return y;
}

__global__ void __launch_bounds__(THREADS)
rnn_warp_per_batch(const float* __restrict__ x_seq,   // [B, T]
                   const float* __restrict__ W_h,     // [H, H]
                   const float* __restrict__ W_x,     // [H, 1]
                   const float* __restrict__ W_y,     // [1, H]
                   float* __restrict__ out)           // [B, T]
{
    __shared__ float hbuf[2][WARPS_PER_CTA][HH];

    const int warp = threadIdx.x >> 5;
    const int lane = threadIdx.x & 31;
    const int b = blockIdx.x * WARPS_PER_CTA + warp;

    const int j0 = 2 * lane;
    const int j1 = 2 * lane + 1;

    // ---- Load weights into registers (one-time cost) ----
    // W_h rows j0, j1 as 32 packed f32x2 pairs each (K-packed).
    u64 wh0[HH / 2], wh1[HH / 2];
    const float2* Wh2 = reinterpret_cast<const float2*>(W_h);
#pragma unroll
    for (int k = 0; k < HH / 2; ++k) {
        float2 a = Wh2[j0 * (HH / 2) + k];
        float2 c = Wh2[j1 * (HH / 2) + k];
        wh0[k] = pack2(a.x, a.y);
        wh1[k] = pack2(c.x, c.y);
    }
    const float wx0 = W_x[j0], wx1 = W_x[j1];
    const float wy0 = W_y[j0], wy1 = W_y[j1];

    // ---- Init hidden state h = 0 in buffer 0 ----
    reinterpret_cast<float2*>(hbuf[0][warp])[lane] = make_float2(0.f, 0.f);
    __syncwarp();

    const float* xp = x_seq + (long)b * TT;
    float* op = out + (long)b * TT;

    // Software-pipelined coalesced x loads: 32 timesteps per 128B warp load.
    float xv = xp[lane];
    int cur = 0;

    for (int t0 = 0; t0 < TT; t0 += 32) {
        float xnext = (t0 + 32 < TT) ? xp[t0 + 32 + lane] : 0.f;
        float ysave = 0.f;

#pragma unroll 2
        for (int s = 0; s < 32; ++s) {
            const float xs = __shfl_sync(0xffffffffu, xv, s);

            const ulonglong2* hc =
                reinterpret_cast<const ulonglong2*>(hbuf[cur][warp]);
            u64 acc0 = 0ull, acc1 = 0ull;
#pragma unroll
            for (int k = 0; k < HH / 4; ++k) {
                ulonglong2 q = hc[k];  // (h[4k],h[4k+1]) , (h[4k+2],h[4k+3])
                acc0 = fma2(q.x, wh0[2 * k],     acc0);
                acc0 = fma2(q.y, wh0[2 * k + 1], acc0);
                acc1 = fma2(q.x, wh1[2 * k],     acc1);
                acc1 = fma2(q.y, wh1[2 * k + 1], acc1);
            }
            float a0l, a0h, a1l, a1h;
            unpack2(acc0, a0l, a0h);
            unpack2(acc1, a1l, a1h);
            const float h0 = tanh_fast(a0l + a0h + xs * wx0);
            const float h1 = tanh_fast(a1l + a1h + xs * wx1);

            const int nxt = cur ^ 1;
            reinterpret_cast<float2*>(hbuf[nxt][warp])[lane] =
                make_float2(h0, h1);
            __syncwarp();

            // y_t = sum_j h_j * W_y[j] — warp butterfly reduce
            float p = h0 * wy0 + h1 * wy1;
            p += __shfl_xor_sync(0xffffffffu, p, 16);
            p += __shfl_xor_sync(0xffffffffu, p, 8);
            p += __shfl_xor_sync(0xffffffffu, p, 4);
            p += __shfl_xor_sync(0xffffffffu, p, 2);
            p += __shfl_xor_sync(0xffffffffu, p, 1);
            // lane s keeps y for timestep t0+s -> coalesced store later
            ysave = (s == lane) ? p : ysave;

            cur = nxt;
        }
        op[t0 + lane] = ysave;  // coalesced 128B store per warp
        xv = xnext;
    }
}

extern "C" void kernel_launch(void* const* d_in, const int* in_sizes, int n_in,
                              void* d_out, int out_size) {
    const float* x_seq = (const float*)d_in[0];  // [1024, 2048, 1]
    const float* W_h   = (const float*)d_in[1];  // [64, 64]
    const float* W_x   = (const float*)d_in[2];  // [64, 1]
    const float* W_y   = (const float*)d_in[3];  // [1, 64]
    float* out = (float*)d_out;                  // [1024, 2048, 1]

    const int blocks = BB / WARPS_PER_CTA;  // 128
    rnn_warp_per_batch<<<blocks, THREADS>>>(x_seq, W_h, W_x, W_y, out);
}

// round 2
// speedup vs baseline: 1.1220x; 1.1220x over previous
#include <cuda_runtime.h>

// SimpleRNN: B=1024, T=2048, I=1, H=64, O=1
//   h_t = tanh(h_{t-1} @ W_h^T + x_t @ W_x^T);  y_t = h_t @ W_y^T
// One warp per batch row, persistent over T. Lane L owns h[2L], h[2L+1].
// W_h rows in registers as packed f32x2; dot products via fma.rn.f32x2 with
// 4 independent accumulator chains (crit path 16 deep). h double-buffered in
// smem. y-partials staged in a padded smem tile, reduced every 32 steps via
// conflict-free transpose read (no per-step shuffle reduce).

#define BB 1024
#define TT 2048
#define HH 64
#define WARPS_PER_CTA 8
#define THREADS (32 * WARPS_PER_CTA)

typedef unsigned long long u64;

__device__ __forceinline__ u64 fma2(u64 a, u64 b, u64 c) {
    u64 d;
    asm("fma.rn.f32x2 %0, %1, %2, %3;" : "=l"(d) : "l"(a), "l"(b), "l"(c));
    return d;
}
__device__ __forceinline__ u64 pack2(float lo, float hi) {
    u64 r;
    asm("mov.b64 %0, {%1, %2};" : "=l"(r) : "f"(lo), "f"(hi));
    return r;
}
__device__ __forceinline__ void unpack2(u64 v, float& lo, float& hi) {
    asm("mov.b64 {%0, %1}, %2;" : "=f"(lo), "=f"(hi) : "l"(v));
}
__device__ __forceinline__ float tanh_fast(float x) {
    float y;
    asm("tanh.approx.f32 %0, %1;" : "=f"(y) : "f"(x));
    return y;
}

__global__ void __launch_bounds__(THREADS)
rnn_warp_per_batch(const float* __restrict__ x_seq,   // [B, T]
                   const float* __restrict__ W_h,     // [H, H]
                   const float* __restrict__ W_x,     // [H, 1]
                   const float* __restrict__ W_y,     // [1, H]
                   float* __restrict__ out)           // [B, T]
{
    __shared__ float hbuf[2][WARPS_PER_CTA][HH];
    __shared__ float pbuf[WARPS_PER_CTA][32][33];  // padded: conflict-free transpose

    const int warp = threadIdx.x >> 5;
    const int lane = threadIdx.x & 31;
    const int b = blockIdx.x * WARPS_PER_CTA + warp;

    const int j0 = 2 * lane;
    const int j1 = 2 * lane + 1;

    // ---- Weights into registers ----
    u64 wh0[HH / 2], wh1[HH / 2];
    const float2* Wh2 = reinterpret_cast<const float2*>(W_h);
#pragma unroll
    for (int k = 0; k < HH / 2; ++k) {
        float2 a = Wh2[j0 * (HH / 2) + k];
        float2 c = Wh2[j1 * (HH / 2) + k];
        wh0[k] = pack2(a.x, a.y);
        wh1[k] = pack2(c.x, c.y);
    }
    const float wx0 = W_x[j0], wx1 = W_x[j1];
    const float wy0 = W_y[j0], wy1 = W_y[j1];

    // ---- h = 0 in buffer 0 ----
    reinterpret_cast<float2*>(hbuf[0][warp])[lane] = make_float2(0.f, 0.f);
    __syncwarp();

    const float* xp = x_seq + (long)b * TT;
    float* op = out + (long)b * TT;

    float xv = xp[lane];  // 32 timesteps of x per 128B coalesced load
    int cur = 0;

    for (int t0 = 0; t0 < TT; t0 += 32) {
        float xnext = (t0 + 32 < TT) ? xp[t0 + 32 + lane] : 0.f;

#pragma unroll 2
        for (int s = 0; s < 32; ++s) {
            const float xs = __shfl_sync(0xffffffffu, xv, s);

            const ulonglong2* hc =
                reinterpret_cast<const ulonglong2*>(hbuf[cur][warp]);

            // 4 independent chains, 16 deep each; xs*wx folded into init.
            u64 acc0a = pack2(xs * wx0, 0.f);
            u64 acc0b = 0ull;
            u64 acc1a = pack2(xs * wx1, 0.f);
            u64 acc1b = 0ull;
#pragma unroll
            for (int k = 0; k < HH / 8; ++k) {           // 8 iters
                ulonglong2 qa = hc[2 * k];
                ulonglong2 qb = hc[2 * k + 1];
                acc0a = fma2(qa.x, wh0[4 * k],     acc0a);
                acc0a = fma2(qa.y, wh0[4 * k + 1], acc0a);
                acc1a = fma2(qa.x, wh1[4 * k],     acc1a);
                acc1a = fma2(qa.y, wh1[4 * k + 1], acc1a);
                acc0b = fma2(qb.x, wh0[4 * k + 2], acc0b);
                acc0b = fma2(qb.y, wh0[4 * k + 3], acc0b);
                acc1b = fma2(qb.x, wh1[4 * k + 2], acc1b);
                acc1b = fma2(qb.y, wh1[4 * k + 3], acc1b);
            }
            float a0, a1, b0, b1, c0, c1, d0, d1;
            unpack2(acc0a, a0, a1);
            unpack2(acc0b, b0, b1);
            unpack2(acc1a, c0, c1);
            unpack2(acc1b, d0, d1);
            const float h0 = tanh_fast((a0 + a1) + (b0 + b1));
            const float h1 = tanh_fast((c0 + c1) + (d0 + d1));

            const int nxt = cur ^ 1;
            reinterpret_cast<float2*>(hbuf[nxt][warp])[lane] =
                make_float2(h0, h1);
            // y-partial -> padded tile (reduced after the 32-step block)
            pbuf[warp][s][lane] = fmaf(h0, wy0, h1 * wy1);
            __syncwarp();

            cur = nxt;
        }

        // y[t0+L] = sum over lanes of pbuf[L][lane]; stride-33 rows are
        // conflict-free when lane L reads row L.
        float s0 = 0.f, s1 = 0.f, s2 = 0.f, s3 = 0.f;
#pragma unroll
        for (int i = 0; i < 32; i += 4) {
            s0 += pbuf[warp][lane][i];
            s1 += pbuf[warp][lane][i + 1];
            s2 += pbuf[warp][lane][i + 2];
            s3 += pbuf[warp][lane][i + 3];
        }
        op[t0 + lane] = (s0 + s1) + (s2 + s3);  // coalesced 128B store
        __syncwarp();

        xv = xnext;
    }
}

extern "C" void kernel_launch(void* const* d_in, const int* in_sizes, int n_in,
                              void* d_out, int out_size) {
    const float* x_seq = (const float*)d_in[0];  // [1024, 2048, 1]
    const float* W_h   = (const float*)d_in[1];  // [64, 64]
    const float* W_x   = (const float*)d_in[2];  // [64, 1]
    const float* W_y   = (const float*)d_in[3];  // [1, 64]
    float* out = (float*)d_out;                  // [1024, 2048, 1]

    const int blocks = BB / WARPS_PER_CTA;  // 128
    rnn_warp_per_batch<<<blocks, THREADS>>>(x_seq, W_h, W_x, W_y, out);
}